// round 11
// baseline (speedup 1.0000x reference)
#include <cuda_runtime.h>

// Problem constants
#define KCODES   512
#define DIM      64
#define HW       4096      // 64*64
#define NBATCH   32
#define PIXB     256       // pixels per block
#define THREADS  512       // 16 warps -> 4 per SMSP (latency hiding)
#define NBLK     512       // (NBATCH*HW)/PIXB
#define TILES_PER_IMG 16   // HW/PIXB
#define ES_STRIDE 68       // padded row stride (floats) for codebook in smem
#define XS_STRIDE 68       // padded row stride (floats) for pixel tile in smem
#define TAU      2e-3f     // fp32 top-2 margin below which we refine in fp64

// device scratch (static allocation — allowed)
__device__ double       g_part[NBLK];
__device__ unsigned int g_done = 0;   // self-resetting via atomicInc wraparound

// packed dual-FP32 FMA: acc.{lo,hi} += a.{lo,hi} * b.{lo,hi}
__device__ __forceinline__ void ffma2(unsigned long long &acc,
                                      unsigned long long a,
                                      unsigned long long b) {
    asm("fma.rn.f32x2 %0, %1, %2, %0;" : "+l"(acc) : "l"(a), "l"(b));
}

__global__ __launch_bounds__(THREADS, 1)
void vq_main(const float* __restrict__ feat,
             const float* __restrict__ emb,
             float* __restrict__ out, int last) {
    extern __shared__ float sm[];
    float* es    = sm;                               // [512][68]
    float* xs    = es + KCODES * ES_STRIDE;          // [256][68]
    float* e2s   = xs + PIXB * XS_STRIDE;            // [512]
    int*   bestk = (int*)(e2s + KCODES);             // [256]
    float* wsum  = (float*)(bestk + PIXB);           // [16]
    int*   nflag = (int*)(wsum + 16);                // [1]
    int*   flags = nflag + 1;                        // [256]

    __shared__ int    s_last;
    __shared__ double s_red[THREADS];

    const int t   = threadIdx.x;
    const int bid = blockIdx.x;
    const int b   = bid >> 4;                         // 16 tiles per image
    const int p0  = (bid & (TILES_PER_IMG - 1)) * PIXB;
    const float* fbase = feat + ((size_t)b * DIM) * HW + p0;

    if (t == 0) *nflag = 0;

    // ---- stage codebook into smem (natural [k][d], padded rows, float4) ----
    {
        const float4* g4 = (const float4*)emb;
        for (int i = t; i < KCODES * (DIM / 4); i += THREADS) {
            int k  = i >> 4;
            int d4 = i & 15;
            *(float4*)&es[k * ES_STRIDE + d4 * 4] = g4[i];
        }
    }
    // ---- stage 256-pixel tile, transposing NCHW [d][p] -> xs[p][d] ----
    for (int i = t; i < PIXB * DIM; i += THREADS) {
        int d = i >> 8;
        int p = i & (PIXB - 1);
        xs[p * XS_STRIDE + d] = fbase[(size_t)d * HW + p];
    }
    __syncthreads();

    // ---- per-code squared norms ----
    for (int k = t; k < KCODES; k += THREADS) {
        const float* er = &es[k * ES_STRIDE];
        float s = 0.f;
        #pragma unroll
        for (int d = 0; d < DIM; d++) s = fmaf(er[d], er[d], s);
        e2s[k] = s;
    }
    __syncthreads();

    // ---- GEMM-style distance + top-2 argmin ----
    // thread tile: 4 pixels x 8 codes.
    //   pixels: pg + j*64   (j = 0..3)  -> x LDS conflict-free (row stride 1 in pg)
    //   codes:  kc*64 + jj*8 + kg       -> ev LDS conflict-free (row stride 1 in kg)
    const int pg = t >> 3;   // 0..63
    const int kg = t & 7;    // 0..7

    float s1[4], s2[4];
    int   i1[4];
    #pragma unroll
    for (int j = 0; j < 4; j++) { s1[j] = 3.4e38f; s2[j] = 3.4e38f; i1[j] = 0; }

    const float* xbase = &xs[pg * XS_STRIDE];

    for (int kc = 0; kc < 8; kc++) {
        const int kbase = kc * 64 + kg;
        const float* erow = &es[kbase * ES_STRIDE];

        unsigned long long acc[4][8];
        #pragma unroll
        for (int j = 0; j < 4; j++)
            #pragma unroll
            for (int jj = 0; jj < 8; jj++) acc[j][jj] = 0ULL;

        // unroll 1: keep live register set under the 128-reg cap (no spills)
        #pragma unroll 1
        for (int d4 = 0; d4 < 16; d4++) {
            ulonglong2 xv0 = *(const ulonglong2*)&xbase[0 * 64 * XS_STRIDE + d4 * 4];
            ulonglong2 xv1 = *(const ulonglong2*)&xbase[1 * 64 * XS_STRIDE + d4 * 4];
            ulonglong2 xv2 = *(const ulonglong2*)&xbase[2 * 64 * XS_STRIDE + d4 * 4];
            ulonglong2 xv3 = *(const ulonglong2*)&xbase[3 * 64 * XS_STRIDE + d4 * 4];
            #pragma unroll
            for (int jj = 0; jj < 8; jj++) {
                ulonglong2 ev =
                    *(const ulonglong2*)&erow[jj * 8 * ES_STRIDE + d4 * 4];
                // interleaved: 4 independent accs between reuses (no RAW stall)
                ffma2(acc[0][jj], xv0.x, ev.x);
                ffma2(acc[1][jj], xv1.x, ev.x);
                ffma2(acc[2][jj], xv2.x, ev.x);
                ffma2(acc[3][jj], xv3.x, ev.x);
                ffma2(acc[0][jj], xv0.y, ev.y);
                ffma2(acc[1][jj], xv1.y, ev.y);
                ffma2(acc[2][jj], xv2.y, ev.y);
                ffma2(acc[3][jj], xv3.y, ev.y);
            }
        }

        // epilogue: score = e2 - 2*dot ; top-2 (strict <, ascending code order)
        #pragma unroll
        for (int jj = 0; jj < 8; jj++) {
            const int code = kbase + jj * 8;
            const float e2v = e2s[code];
            #pragma unroll
            for (int j = 0; j < 4; j++) {
                unsigned long long a = acc[j][jj];
                float lo = __uint_as_float((unsigned)a);
                float hi = __uint_as_float((unsigned)(a >> 32));
                float dot = lo + hi;
                float score = fmaf(-2.f, dot, e2v);
                if (score < s1[j]) { s2[j] = s1[j]; s1[j] = score; i1[j] = code; }
                else if (score < s2[j]) { s2[j] = score; }
            }
        }
    }

    // ---- reduce top-2 across the 8 kg-lanes (same pg), tie -> smaller index ----
    #pragma unroll
    for (int j = 0; j < 4; j++) {
        float a1 = s1[j], a2 = s2[j];
        int   ai = i1[j];
        #pragma unroll
        for (int off = 1; off < 8; off <<= 1) {
            float o1 = __shfl_xor_sync(0xffffffffu, a1, off);
            int   oi = __shfl_xor_sync(0xffffffffu, ai, off);
            float o2 = __shfl_xor_sync(0xffffffffu, a2, off);
            if (o1 < a1 || (o1 == a1 && oi < ai)) {
                a2 = fminf(a1, o2); a1 = o1; ai = oi;
            } else {
                a2 = fminf(a2, o1);
            }
        }
        if (kg == 0) {
            const int p = j * 64 + pg;
            bestk[p] = ai;
            if (a2 - a1 < TAU) {
                int slot = atomicAdd(nflag, 1);
                flags[slot] = p;
            }
        }
    }
    __syncthreads();

    // ---- fp64 exact refinement of near-tie pixels (one warp per pixel) ----
    {
        const int nf   = *nflag;
        const int wid  = t >> 5;   // 16 warps
        const int lane = t & 31;
        for (int f = wid; f < nf; f += 16) {
            const int p = flags[f];
            const float* xr = &xs[p * XS_STRIDE];
            double bs = 1e300;
            int    bi = 0x7fffffff;
            for (int k = lane; k < KCODES; k += 32) {
                const float* er = &es[k * ES_STRIDE];
                double a0 = 0.0, a1d = 0.0, a2d = 0.0, a3d = 0.0;
                #pragma unroll
                for (int d = 0; d < DIM; d += 4) {
                    double d0 = (double)xr[d + 0] - (double)er[d + 0];
                    double d1 = (double)xr[d + 1] - (double)er[d + 1];
                    double d2 = (double)xr[d + 2] - (double)er[d + 2];
                    double d3 = (double)xr[d + 3] - (double)er[d + 3];
                    a0  = fma(d0, d0, a0);
                    a1d = fma(d1, d1, a1d);
                    a2d = fma(d2, d2, a2d);
                    a3d = fma(d3, d3, a3d);
                }
                double s = (a0 + a1d) + (a2d + a3d);
                if (s < bs) { bs = s; bi = k; }   // ascending k -> first occurrence
            }
            #pragma unroll
            for (int off = 16; off > 0; off >>= 1) {
                double os = __shfl_xor_sync(0xffffffffu, bs, off);
                int    oi = __shfl_xor_sync(0xffffffffu, bi, off);
                if (os < bs || (os == bs && oi < bi)) { bs = os; bi = oi; }
            }
            if (lane == 0) bestk[p] = bi;
        }
    }
    __syncthreads();

    // ---- gather output (NCHW) + elementwise-exact loss partial ----
    float lsum = 0.f;
    float* outb = out + ((size_t)b * DIM) * HW + p0;
    for (int i = t; i < PIXB * DIM; i += THREADS) {
        int d = i >> 8;
        int p = i & (PIXB - 1);
        int k = bestk[p];
        float ev = es[k * ES_STRIDE + d];
        float xv = xs[p * XS_STRIDE + d];
        outb[(size_t)d * HW + p] = ev;     // st == quant_out (forward value)
        float df = ev - xv;
        lsum = fmaf(df, df, lsum);
    }
    #pragma unroll
    for (int off = 16; off > 0; off >>= 1)
        lsum += __shfl_xor_sync(0xffffffffu, lsum, off);
    if ((t & 31) == 0) wsum[t >> 5] = lsum;
    __syncthreads();

    // ---- fused loss finalization: last block reduces all partials ----
    if (t == 0) {
        double s = 0.0;
        #pragma unroll
        for (int w = 0; w < 16; w++) s += (double)wsum[w];
        g_part[bid] = s;
        __threadfence();
        unsigned int old = atomicInc(&g_done, NBLK - 1);  // wraps to 0 => reset
        s_last = (old == NBLK - 1);
    }
    __syncthreads();

    if (s_last) {
        // deterministic fixed-order reduction of 512 partials
        s_red[t] = g_part[t];
        __syncthreads();
        #pragma unroll
        for (int sred = THREADS / 2; sred > 0; sred >>= 1) {
            if (t < sred) s_red[t] += s_red[t + sred];
            __syncthreads();
        }
        if (t == 0) {
            // loss = commitment + beta*codebook = 1.2 * mean(min dist^2)
            out[last] = (float)(1.2 * s_red[0]
                                / (double)(NBATCH * DIM * HW));
        }
    }
}

extern "C" void kernel_launch(void* const* d_in, const int* in_sizes, int n_in,
                              void* d_out, int out_size) {
    const float* feat = (const float*)d_in[0];   // (32, 64, 64, 64) fp32 NCHW
    const float* emb  = (const float*)d_in[1];   // (512, 64) fp32
    float* out = (float*)d_out;                  // st (8388608 floats) + loss (1)

    const int smem_bytes =
        (KCODES * ES_STRIDE + PIXB * XS_STRIDE + KCODES) * (int)sizeof(float)
        + PIXB * (int)sizeof(int)
        + 16 * (int)sizeof(float)
        + (1 + PIXB) * (int)sizeof(int);

    cudaFuncSetAttribute(vq_main, cudaFuncAttributeMaxDynamicSharedMemorySize,
                         smem_bytes);

    vq_main<<<NBLK, THREADS, smem_bytes>>>(feat, emb, out, out_size - 1);
}

// round 12
// speedup vs baseline: 1.0024x; 1.0024x over previous
#include <cuda_runtime.h>

// Problem constants
#define KCODES   512
#define DIM      64
#define HW       4096      // 64*64
#define NBATCH   32
#define PIXB     256       // pixels per block
#define THREADS  512       // 16 warps -> 4 per SMSP (latency hiding)
#define NBLK     512       // (NBATCH*HW)/PIXB
#define TILES_PER_IMG 16   // HW/PIXB
#define ES_STRIDE 68       // padded row stride (floats) for codebook in smem
#define XS_STRIDE 68       // padded row stride (floats) for pixel tile in smem
#define TAU      2e-3f     // fp32 top-2 margin below which we refine in fp64

// device scratch (static allocation — allowed)
__device__ double       g_part[NBLK];
__device__ unsigned int g_done = 0;   // self-resetting via atomicInc wraparound

// packed dual-FP32 FMA: acc.{lo,hi} += a.{lo,hi} * b.{lo,hi}
__device__ __forceinline__ void ffma2(unsigned long long &acc,
                                      unsigned long long a,
                                      unsigned long long b) {
    asm("fma.rn.f32x2 %0, %1, %2, %0;" : "+l"(acc) : "l"(a), "l"(b));
}

__global__ __launch_bounds__(THREADS, 1)
void vq_main(const float* __restrict__ feat,
             const float* __restrict__ emb,
             float* __restrict__ out, int last) {
    extern __shared__ float sm[];
    float* es    = sm;                               // [512][68]
    float* xs    = es + KCODES * ES_STRIDE;          // [256][68]
    float* e2s   = xs + PIXB * XS_STRIDE;            // [512]
    int*   bestk = (int*)(e2s + KCODES);             // [256]
    float* wsum  = (float*)(bestk + PIXB);           // [16]
    int*   nflag = (int*)(wsum + 16);                // [1]
    int*   flags = nflag + 1;                        // [256]

    __shared__ int    s_last;
    __shared__ double s_red[THREADS];

    const int t   = threadIdx.x;
    const int bid = blockIdx.x;
    const int b   = bid >> 4;                         // 16 tiles per image
    const int p0  = (bid & (TILES_PER_IMG - 1)) * PIXB;
    const float* fbase = feat + ((size_t)b * DIM) * HW + p0;

    if (t == 0) *nflag = 0;

    // ---- stage codebook into smem (natural [k][d], padded rows, float4) ----
    {
        const float4* g4 = (const float4*)emb;
        for (int i = t; i < KCODES * (DIM / 4); i += THREADS) {
            int k  = i >> 4;
            int d4 = i & 15;
            *(float4*)&es[k * ES_STRIDE + d4 * 4] = g4[i];
        }
    }
    // ---- stage 256-pixel tile, transposing NCHW [d][p] -> xs[p][d] ----
    for (int i = t; i < PIXB * DIM; i += THREADS) {
        int d = i >> 8;
        int p = i & (PIXB - 1);
        xs[p * XS_STRIDE + d] = fbase[(size_t)d * HW + p];
    }
    __syncthreads();

    // ---- per-code squared norms ----
    for (int k = t; k < KCODES; k += THREADS) {
        const float* er = &es[k * ES_STRIDE];
        float s = 0.f;
        #pragma unroll
        for (int d = 0; d < DIM; d++) s = fmaf(er[d], er[d], s);
        e2s[k] = s;
    }
    __syncthreads();

    // ---- GEMM-style distance + top-2 argmin ----
    // thread tile: 4 pixels x 8 codes.
    //   pixels: pg + j*64   (j = 0..3)  -> x LDS conflict-free (row stride 1 in pg)
    //   codes:  kc*64 + jj*8 + kg       -> ev LDS conflict-free (row stride 1 in kg)
    const int pg = t >> 3;   // 0..63
    const int kg = t & 7;    // 0..7

    float s1[4], s2[4];
    int   i1[4];
    #pragma unroll
    for (int j = 0; j < 4; j++) { s1[j] = 3.4e38f; s2[j] = 3.4e38f; i1[j] = 0; }

    const float* xbase = &xs[pg * XS_STRIDE];

    for (int kc = 0; kc < 8; kc++) {
        const int kbase = kc * 64 + kg;
        const float* erow = &es[kbase * ES_STRIDE];

        unsigned long long acc[4][8];
        #pragma unroll
        for (int j = 0; j < 4; j++)
            #pragma unroll
            for (int jj = 0; jj < 8; jj++) acc[j][jj] = 0ULL;

        // unroll 1: keep live register set under the 128-reg cap (no spills)
        #pragma unroll 1
        for (int d4 = 0; d4 < 16; d4++) {
            ulonglong2 xv0 = *(const ulonglong2*)&xbase[0 * 64 * XS_STRIDE + d4 * 4];
            ulonglong2 xv1 = *(const ulonglong2*)&xbase[1 * 64 * XS_STRIDE + d4 * 4];
            ulonglong2 xv2 = *(const ulonglong2*)&xbase[2 * 64 * XS_STRIDE + d4 * 4];
            ulonglong2 xv3 = *(const ulonglong2*)&xbase[3 * 64 * XS_STRIDE + d4 * 4];
            #pragma unroll
            for (int jj = 0; jj < 8; jj++) {
                ulonglong2 ev =
                    *(const ulonglong2*)&erow[jj * 8 * ES_STRIDE + d4 * 4];
                // interleaved: 4 independent accs between reuses (no RAW stall)
                ffma2(acc[0][jj], xv0.x, ev.x);
                ffma2(acc[1][jj], xv1.x, ev.x);
                ffma2(acc[2][jj], xv2.x, ev.x);
                ffma2(acc[3][jj], xv3.x, ev.x);
                ffma2(acc[0][jj], xv0.y, ev.y);
                ffma2(acc[1][jj], xv1.y, ev.y);
                ffma2(acc[2][jj], xv2.y, ev.y);
                ffma2(acc[3][jj], xv3.y, ev.y);
            }
        }

        // epilogue: score = e2 - 2*dot ; top-2 (strict <, ascending code order)
        #pragma unroll
        for (int jj = 0; jj < 8; jj++) {
            const int code = kbase + jj * 8;
            const float e2v = e2s[code];
            #pragma unroll
            for (int j = 0; j < 4; j++) {
                unsigned long long a = acc[j][jj];
                float lo = __uint_as_float((unsigned)a);
                float hi = __uint_as_float((unsigned)(a >> 32));
                float dot = lo + hi;
                float score = fmaf(-2.f, dot, e2v);
                if (score < s1[j]) { s2[j] = s1[j]; s1[j] = score; i1[j] = code; }
                else if (score < s2[j]) { s2[j] = score; }
            }
        }
    }

    // ---- reduce top-2 across the 8 kg-lanes (same pg), tie -> smaller index ----
    #pragma unroll
    for (int j = 0; j < 4; j++) {
        float a1 = s1[j], a2 = s2[j];
        int   ai = i1[j];
        #pragma unroll
        for (int off = 1; off < 8; off <<= 1) {
            float o1 = __shfl_xor_sync(0xffffffffu, a1, off);
            int   oi = __shfl_xor_sync(0xffffffffu, ai, off);
            float o2 = __shfl_xor_sync(0xffffffffu, a2, off);
            if (o1 < a1 || (o1 == a1 && oi < ai)) {
                a2 = fminf(a1, o2); a1 = o1; ai = oi;
            } else {
                a2 = fminf(a2, o1);
            }
        }
        if (kg == 0) {
            const int p = j * 64 + pg;
            bestk[p] = ai;
            if (a2 - a1 < TAU) {
                int slot = atomicAdd(nflag, 1);
                flags[slot] = p;
            }
        }
    }
    __syncthreads();

    // ---- fp64 exact refinement of near-tie pixels (one warp per pixel) ----
    {
        const int nf   = *nflag;
        const int wid  = t >> 5;   // 16 warps
        const int lane = t & 31;
        for (int f = wid; f < nf; f += 16) {
            const int p = flags[f];
            const float* xr = &xs[p * XS_STRIDE];
            double bs = 1e300;
            int    bi = 0x7fffffff;
            for (int k = lane; k < KCODES; k += 32) {
                const float* er = &es[k * ES_STRIDE];
                double a0 = 0.0, a1d = 0.0, a2d = 0.0, a3d = 0.0;
                #pragma unroll
                for (int d = 0; d < DIM; d += 4) {
                    double d0 = (double)xr[d + 0] - (double)er[d + 0];
                    double d1 = (double)xr[d + 1] - (double)er[d + 1];
                    double d2 = (double)xr[d + 2] - (double)er[d + 2];
                    double d3 = (double)xr[d + 3] - (double)er[d + 3];
                    a0  = fma(d0, d0, a0);
                    a1d = fma(d1, d1, a1d);
                    a2d = fma(d2, d2, a2d);
                    a3d = fma(d3, d3, a3d);
                }
                double s = (a0 + a1d) + (a2d + a3d);
                if (s < bs) { bs = s; bi = k; }   // ascending k -> first occurrence
            }
            #pragma unroll
            for (int off = 16; off > 0; off >>= 1) {
                double os = __shfl_xor_sync(0xffffffffu, bs, off);
                int    oi = __shfl_xor_sync(0xffffffffu, bi, off);
                if (os < bs || (os == bs && oi < bi)) { bs = os; bi = oi; }
            }
            if (lane == 0) bestk[p] = bi;
        }
    }
    __syncthreads();

    // ---- gather output (NCHW) + elementwise-exact loss partial ----
    float lsum = 0.f;
    float* outb = out + ((size_t)b * DIM) * HW + p0;
    for (int i = t; i < PIXB * DIM; i += THREADS) {
        int d = i >> 8;
        int p = i & (PIXB - 1);
        int k = bestk[p];
        float ev = es[k * ES_STRIDE + d];
        float xv = xs[p * XS_STRIDE + d];
        outb[(size_t)d * HW + p] = ev;     // st == quant_out (forward value)
        float df = ev - xv;
        lsum = fmaf(df, df, lsum);
    }
    #pragma unroll
    for (int off = 16; off > 0; off >>= 1)
        lsum += __shfl_xor_sync(0xffffffffu, lsum, off);
    if ((t & 31) == 0) wsum[t >> 5] = lsum;
    __syncthreads();

    // ---- fused loss finalization: last block reduces all partials ----
    if (t == 0) {
        double s = 0.0;
        #pragma unroll
        for (int w = 0; w < 16; w++) s += (double)wsum[w];
        g_part[bid] = s;
        __threadfence();
        unsigned int old = atomicInc(&g_done, NBLK - 1);  // wraps to 0 => reset
        s_last = (old == NBLK - 1);
    }
    __syncthreads();

    if (s_last) {
        // deterministic fixed-order reduction of 512 partials
        s_red[t] = g_part[t];
        __syncthreads();
        #pragma unroll
        for (int sred = THREADS / 2; sred > 0; sred >>= 1) {
            if (t < sred) s_red[t] += s_red[t + sred];
            __syncthreads();
        }
        if (t == 0) {
            // loss = commitment + beta*codebook = 1.2 * mean(min dist^2)
            out[last] = (float)(1.2 * s_red[0]
                                / (double)(NBATCH * DIM * HW));
        }
    }
}

extern "C" void kernel_launch(void* const* d_in, const int* in_sizes, int n_in,
                              void* d_out, int out_size) {
    const float* feat = (const float*)d_in[0];   // (32, 64, 64, 64) fp32 NCHW
    const float* emb  = (const float*)d_in[1];   // (512, 64) fp32
    float* out = (float*)d_out;                  // st (8388608 floats) + loss (1)

    const int smem_bytes =
        (KCODES * ES_STRIDE + PIXB * XS_STRIDE + KCODES) * (int)sizeof(float)
        + PIXB * (int)sizeof(int)
        + 16 * (int)sizeof(float)
        + (1 + PIXB) * (int)sizeof(int);

    cudaFuncSetAttribute(vq_main, cudaFuncAttributeMaxDynamicSharedMemorySize,
                         smem_bytes);

    vq_main<<<NBLK, THREADS, smem_bytes>>>(feat, emb, out, out_size - 1);
}